// round 5
// baseline (speedup 1.0000x reference)
#include <cuda_runtime.h>
#include <cuda_bf16.h>
#include <cstdint>

// ======================= constants =======================
#define B_SZ   1024
#define LQ     16
#define LKV    128
#define DIM    512
#define NH     8
#define DH     64

#define MQ     (B_SZ*LQ)     // 16384
#define MKV    (B_SZ*LKV)    // 131072

// ======================= scratch (device globals; no allocs allowed) =======================
__device__ float g_xnorm[MQ * DIM];
__device__ float g_Q[MQ * DIM];
__device__ float g_K[67108864];   // MKV * DIM
__device__ float g_V[67108864];
__device__ float g_O[MQ * DIM];
__device__ __nv_bfloat16 g_Whi[4 * DIM * DIM];   // transposed [n][k], hi part
__device__ __nv_bfloat16 g_Wlo[4 * DIM * DIM];   // transposed [n][k], lo part

// ======================= helpers =======================
__device__ __forceinline__ uint32_t smem_u32(const void* p) {
    uint32_t a;
    asm("{ .reg .u64 t; cvta.to.shared.u64 t, %1; cvt.u32.u64 %0, t; }" : "=r"(a) : "l"(p));
    return a;
}

#define CP16(dst, src) \
    asm volatile("cp.async.cg.shared.global [%0], [%1], 16;" :: "r"(dst), "l"(src) : "memory")
#define CP_COMMIT() asm volatile("cp.async.commit_group;" ::: "memory")
#define CP_WAIT0()  asm volatile("cp.async.wait_group 0;" ::: "memory")

__device__ __forceinline__ void ldsm_x4(uint32_t* r, uint32_t addr) {
    asm volatile("ldmatrix.sync.aligned.m8n8.x4.shared.b16 {%0,%1,%2,%3}, [%4];"
                 : "=r"(r[0]), "=r"(r[1]), "=r"(r[2]), "=r"(r[3]) : "r"(addr));
}

__device__ __forceinline__ void mma_bf16(float* d, const uint32_t* a, uint32_t b0, uint32_t b1) {
    asm volatile("mma.sync.aligned.m16n8k16.row.col.f32.bf16.bf16.f32 "
                 "{%0,%1,%2,%3}, {%4,%5,%6,%7}, {%8,%9}, {%0,%1,%2,%3};"
                 : "+f"(d[0]), "+f"(d[1]), "+f"(d[2]), "+f"(d[3])
                 : "r"(a[0]), "r"(a[1]), "r"(a[2]), "r"(a[3]), "r"(b0), "r"(b1));
}

// XOR swizzle: row has 32 halves (64B) = 4 chunks of 16B; chunk ^= (row>>1)&3.
// Conflict-free for ldmatrix 8-row phases and STS.128 staging (verified by bank enum).
__device__ __forceinline__ uint32_t swz(int row, int kchunk) {
    return (uint32_t)(row * 64 + ((kchunk ^ ((row >> 1) & 3)) << 4));
}

__device__ __forceinline__ void split8_pack(const float* f, uint4& hv, uint4& lv) {
    unsigned short hs[8], ls[8];
#pragma unroll
    for (int i = 0; i < 8; i++) {
        __nv_bfloat16 h = __float2bfloat16(f[i]);
        __nv_bfloat16 l = __float2bfloat16(f[i] - __bfloat162float(h));
        hs[i] = __bfloat16_as_ushort(h);
        ls[i] = __bfloat16_as_ushort(l);
    }
    hv.x = (uint32_t)hs[0] | ((uint32_t)hs[1] << 16);
    hv.y = (uint32_t)hs[2] | ((uint32_t)hs[3] << 16);
    hv.z = (uint32_t)hs[4] | ((uint32_t)hs[5] << 16);
    hv.w = (uint32_t)hs[6] | ((uint32_t)hs[7] << 16);
    lv.x = (uint32_t)ls[0] | ((uint32_t)ls[1] << 16);
    lv.y = (uint32_t)ls[2] | ((uint32_t)ls[3] << 16);
    lv.z = (uint32_t)ls[4] | ((uint32_t)ls[5] << 16);
    lv.w = (uint32_t)ls[6] | ((uint32_t)ls[7] << 16);
}

// ======================= prep: split W^T into bf16 hi/lo =======================
__global__ void prep_weights(const float* __restrict__ Wq, const float* __restrict__ Wk,
                             const float* __restrict__ Wv, const float* __restrict__ Wo) {
    int idx = blockIdx.x * 256 + threadIdx.x;          // 0 .. 4*512*512-1
    int w = idx >> 18;
    int r = idx & 262143;
    int n = r & 511;      // output col of W = row of B
    int k = r >> 9;       // input dim
    const float* W = (w == 0) ? Wq : (w == 1) ? Wk : (w == 2) ? Wv : Wo;
    float v = W[k * DIM + n];
    __nv_bfloat16 h = __float2bfloat16(v);
    float rem = v - __bfloat162float(h);
    g_Whi[w * DIM * DIM + n * DIM + k] = h;
    g_Wlo[w * DIM * DIM + n * DIM + k] = __float2bfloat16(rem);
}

// ======================= LayerNorm =======================
__global__ void ln_kernel(const float* __restrict__ x, const float* __restrict__ gamma,
                          const float* __restrict__ beta, float* __restrict__ out) {
    int warp = threadIdx.x >> 5;
    int lane = threadIdx.x & 31;
    size_t row = (size_t)blockIdx.x * 8 + warp;
    const float* xr = x + row * DIM;
    float4 v[4];
    float s = 0.f, ss = 0.f;
#pragma unroll
    for (int j = 0; j < 4; j++) {
        v[j] = *(const float4*)(xr + j * 128 + lane * 4);
        s  += v[j].x + v[j].y + v[j].z + v[j].w;
        ss += v[j].x * v[j].x + v[j].y * v[j].y + v[j].z * v[j].z + v[j].w * v[j].w;
    }
#pragma unroll
    for (int o = 16; o > 0; o >>= 1) {
        s  += __shfl_xor_sync(0xFFFFFFFFu, s, o);
        ss += __shfl_xor_sync(0xFFFFFFFFu, ss, o);
    }
    float mu  = s * (1.0f / DIM);
    float var = ss * (1.0f / DIM) - mu * mu;
    float inv = rsqrtf(var + 1e-5f);
    float* orow = out + row * DIM;
#pragma unroll
    for (int j = 0; j < 4; j++) {
        int c = j * 128 + lane * 4;
        float4 g = *(const float4*)(gamma + c);
        float4 be = *(const float4*)(beta + c);
        float4 r;
        r.x = (v[j].x - mu) * inv * g.x + be.x;
        r.y = (v[j].y - mu) * inv * g.y + be.y;
        r.z = (v[j].z - mu) * inv * g.z + be.z;
        r.w = (v[j].w - mu) * inv * g.w + be.w;
        *(float4*)(orow + c) = r;
    }
}

// ======================= GEMM: C[M,512] = A[M,512] @ W + bias (+res) =======================
// mma.sync m16n8k16 bf16, hi/lo split (3 MMAs). CTA 128x128, BK=32, 256 thr, double-buffered.
#define BM 128
#define BN 128
#define BK 32
#define OFF_AHI 0
#define OFF_ALO 8192
#define OFF_BHI 16384
#define OFF_BLO 24576
#define STAGE_BYTES 32768
#define GEMM_SMEM (2 * STAGE_BYTES)

__global__ void __launch_bounds__(256) gemm_kernel(
    const float* __restrict__ A,
    const __nv_bfloat16* __restrict__ Bhi1, const __nv_bfloat16* __restrict__ Blo1,
    const float* __restrict__ bias1, float* __restrict__ C1,
    const __nv_bfloat16* __restrict__ Bhi2, const __nv_bfloat16* __restrict__ Blo2,
    const float* __restrict__ bias2, float* __restrict__ C2,
    const float* __restrict__ residual, int nx1)
{
    extern __shared__ char smc[];
    uint32_t sb = smem_u32(smc);
    const int t = threadIdx.x, lane = t & 31, wid = t >> 5;
    const int wm = wid & 1, wn = wid >> 1;        // warp tile 64(m) x 32(n)
    const int m0 = blockIdx.y * BM;

    const __nv_bfloat16 *Bhi, *Blo; const float* bias; float* C;
    int xt = blockIdx.x;
    if (xt < nx1) { Bhi = Bhi1; Blo = Blo1; bias = bias1; C = C1; }
    else          { Bhi = Bhi2; Blo = Blo2; bias = bias2; C = C2; xt -= nx1; }
    const int n0 = xt * BN;

    // ---- staging lambdas ----
    const int arow = t >> 1, ahalf = t & 1;       // thread: 1 row-half (16 fp32)
    auto loadA = [&](int k0, float4* ar) {
        const float* src = A + (size_t)(m0 + arow) * DIM + k0 + ahalf * 16;
#pragma unroll
        for (int i = 0; i < 4; i++) ar[i] = ((const float4*)src)[i];
    };
    auto storeA = [&](uint32_t sbase, const float4* ar) {
        float f[8];
#pragma unroll
        for (int c = 0; c < 2; c++) {
            f[0] = ar[c*2].x; f[1] = ar[c*2].y; f[2] = ar[c*2].z; f[3] = ar[c*2].w;
            f[4] = ar[c*2+1].x; f[5] = ar[c*2+1].y; f[6] = ar[c*2+1].z; f[7] = ar[c*2+1].w;
            uint4 hv, lv;
            split8_pack(f, hv, lv);
            uint32_t off = swz(arow, ahalf * 2 + c);
            *(uint4*)(smc + ((sbase - sb) + OFF_AHI + off)) = hv;
            *(uint4*)(smc + ((sbase - sb) + OFF_ALO + off)) = lv;
        }
    };
    auto stageB = [&](int k0, uint32_t sbase) {
#pragma unroll
        for (int j = 0; j < 2; j++) {
            int id = t + j * 256;
            int n = id >> 2, c = id & 3;
            const __nv_bfloat16* sh = Bhi + (size_t)(n0 + n) * DIM + k0 + c * 8;
            const __nv_bfloat16* sl = Blo + (size_t)(n0 + n) * DIM + k0 + c * 8;
            uint32_t off = swz(n, c);
            CP16(sbase + OFF_BHI + off, sh);
            CP16(sbase + OFF_BLO + off, sl);
        }
    };

    float acc[4][4][4];
#pragma unroll
    for (int i = 0; i < 4; i++)
#pragma unroll
        for (int j = 0; j < 4; j++)
#pragma unroll
            for (int q = 0; q < 4; q++) acc[i][j][q] = 0.f;

    // ---- prologue: stage 0 ----
    {
        stageB(0, sb);
        CP_COMMIT();
        float4 ar[4];
        loadA(0, ar);
        storeA(sb, ar);
        CP_WAIT0();
    }
    __syncthreads();

    // ---- main loop over 16 K-chunks ----
    for (int s = 0; s < 16; s++) {
        uint32_t cbase = sb + (uint32_t)(s & 1) * STAGE_BYTES;
        uint32_t nbase = sb + (uint32_t)((s + 1) & 1) * STAGE_BYTES;
        float4 ar[4];
        if (s < 15) {
            stageB((s + 1) * BK, nbase);
            CP_COMMIT();
            loadA((s + 1) * BK, ar);
        }
        // compute current stage
#pragma unroll
        for (int k16 = 0; k16 < 2; k16++) {
            uint32_t Ah[4][4], Al[4][4], Bh[2][4], Bl[2][4];
            int khalf = lane >> 4;                 // 0/1 -> +8 halves
#pragma unroll
            for (int mt = 0; mt < 4; mt++) {
                int row = wm * 64 + mt * 16 + (lane & 15);
                uint32_t off = swz(row, k16 * 2 + khalf);
                ldsm_x4(Ah[mt], cbase + OFF_AHI + off);
                ldsm_x4(Al[mt], cbase + OFF_ALO + off);
            }
#pragma unroll
            for (int np = 0; np < 2; np++) {
                int row = wn * 32 + np * 16 + (lane & 15);
                uint32_t off = swz(row, k16 * 2 + khalf);
                ldsm_x4(Bh[np], cbase + OFF_BHI + off);
                ldsm_x4(Bl[np], cbase + OFF_BLO + off);
            }
#pragma unroll
            for (int mt = 0; mt < 4; mt++) {
#pragma unroll
                for (int nt = 0; nt < 4; nt++) {
                    int np = nt >> 1, i = nt & 1;
                    mma_bf16(acc[mt][nt], Ah[mt], Bh[np][i], Bh[np][i + 2]);
                    mma_bf16(acc[mt][nt], Ah[mt], Bl[np][i], Bl[np][i + 2]);
                    mma_bf16(acc[mt][nt], Al[mt], Bh[np][i], Bh[np][i + 2]);
                }
            }
        }
        if (s < 15) {
            storeA(nbase, ar);
            CP_WAIT0();
        }
        __syncthreads();
    }

    // ---- epilogue ----
    const int qr = lane >> 2, qc = lane & 3;
#pragma unroll
    for (int mt = 0; mt < 4; mt++) {
#pragma unroll
        for (int nt = 0; nt < 4; nt++) {
            int r = m0 + wm * 64 + mt * 16 + qr;
            int c = n0 + wn * 32 + nt * 8 + qc * 2;
            float b0 = __ldg(bias + c), b1 = __ldg(bias + c + 1);
            float v0 = acc[mt][nt][0] + b0;
            float v1 = acc[mt][nt][1] + b1;
            float v2 = acc[mt][nt][2] + b0;
            float v3 = acc[mt][nt][3] + b1;
            if (residual) {
                float2 r0 = *(const float2*)(residual + (size_t)r * DIM + c);
                float2 r1 = *(const float2*)(residual + (size_t)(r + 8) * DIM + c);
                v0 += r0.x; v1 += r0.y; v2 += r1.x; v3 += r1.y;
            }
            *(float2*)(C + (size_t)r * DIM + c)       = make_float2(v0, v1);
            *(float2*)(C + (size_t)(r + 8) * DIM + c) = make_float2(v2, v3);
        }
    }
}

// ======================= attention: CTA per (b, h) =======================
// smem floats: Qs[16][68], Ks[128][68], Vs[128][68], Ps[16][132]
#define A_QS  0
#define A_KS  (16 * 68)
#define A_VS  (A_KS + 128 * 68)
#define A_PS  (A_VS + 128 * 68)
#define ATTN_SMEM ((A_PS + 16 * 132) * 4)

__global__ void __launch_bounds__(128) attn_kernel(
    const float* __restrict__ Q, const float* __restrict__ K, const float* __restrict__ V,
    const float* __restrict__ rel_bias, float* __restrict__ O) {
    extern __shared__ float smf[];
    float* Qs = smf + A_QS;
    float* Ks = smf + A_KS;
    float* Vs = smf + A_VS;
    float* Ps = smf + A_PS;
    int t = threadIdx.x;
    int bh = blockIdx.x;
    int b = bh >> 3, h = bh & 7;
    const float* Qg = Q + ((size_t)b * LQ) * DIM + h * DH;
    const float* Kg = K + ((size_t)b * LKV) * DIM + h * DH;
    const float* Vg = V + ((size_t)b * LKV) * DIM + h * DH;

    {   // load Q: 16x64
        int q = t >> 3, c = (t & 7) * 8;
        float4 v0 = *(const float4*)(Qg + (size_t)q * DIM + c);
        float4 v1 = *(const float4*)(Qg + (size_t)q * DIM + c + 4);
        *(float4*)(Qs + q * 68 + c) = v0;
        *(float4*)(Qs + q * 68 + c + 4) = v1;
    }
    for (int idx = t; idx < 128 * 16; idx += 128) {   // K,V: 128x64 each
        int r = idx >> 4, c = (idx & 15) * 4;
        *(float4*)(Ks + r * 68 + c) = *(const float4*)(Kg + (size_t)r * DIM + c);
        *(float4*)(Vs + r * 68 + c) = *(const float4*)(Vg + (size_t)r * DIM + c);
    }
    __syncthreads();

    // scores: thread covers q in {tq, tq+8}, kv in [kv0, kv0+8)
    {
        int tq = t & 7, kv0 = (t >> 3) * 8;
        float acc0[8], acc1[8];
#pragma unroll
        for (int j = 0; j < 8; j++) { acc0[j] = 0.f; acc1[j] = 0.f; }
#pragma unroll
        for (int d4 = 0; d4 < 16; d4++) {
            float4 qa = *(float4*)(Qs + tq * 68 + d4 * 4);
            float4 qb = *(float4*)(Qs + (tq + 8) * 68 + d4 * 4);
#pragma unroll
            for (int j = 0; j < 8; j++) {
                float4 kk = *(float4*)(Ks + (kv0 + j) * 68 + d4 * 4);
                acc0[j] += qa.x * kk.x + qa.y * kk.y + qa.z * kk.z + qa.w * kk.w;
                acc1[j] += qb.x * kk.x + qb.y * kk.y + qb.z * kk.z + qb.w * kk.w;
            }
        }
        const float* bsrc = rel_bias + (size_t)h * LQ * LKV;
#pragma unroll
        for (int j = 0; j < 8; j++) {
            Ps[tq * 132 + kv0 + j]       = acc0[j] * 0.125f + bsrc[tq * LKV + kv0 + j];
            Ps[(tq + 8) * 132 + kv0 + j] = acc1[j] * 0.125f + bsrc[(tq + 8) * LKV + kv0 + j];
        }
    }
    __syncthreads();
    if (t < 16) {   // softmax per row
        float m = -1e30f;
        for (int k = 0; k < 128; k++) m = fmaxf(m, Ps[t * 132 + k]);
        float s = 0.f;
        for (int k = 0; k < 128; k++) { float e = __expf(Ps[t * 132 + k] - m); Ps[t * 132 + k] = e; s += e; }
        float inv = 1.0f / s;
        for (int k = 0; k < 128; k++) Ps[t * 132 + k] *= inv;
    }
    __syncthreads();
    {   // out = attn @ V : thread -> (q, 8 d-cols)
        int q = t >> 3, d0 = (t & 7) * 8;
        float o[8];
#pragma unroll
        for (int i = 0; i < 8; i++) o[i] = 0.f;
#pragma unroll 8
        for (int kv = 0; kv < 128; kv++) {
            float a = Ps[q * 132 + kv];
            float4 va = *(float4*)(Vs + kv * 68 + d0);
            float4 vb = *(float4*)(Vs + kv * 68 + d0 + 4);
            o[0] += a * va.x; o[1] += a * va.y; o[2] += a * va.z; o[3] += a * va.w;
            o[4] += a * vb.x; o[5] += a * vb.y; o[6] += a * vb.z; o[7] += a * vb.w;
        }
        float* Og = O + ((size_t)b * LQ + q) * DIM + h * DH + d0;
        *(float4*)Og       = make_float4(o[0], o[1], o[2], o[3]);
        *(float4*)(Og + 4) = make_float4(o[4], o[5], o[6], o[7]);
    }
}

// ======================= launch =======================
extern "C" void kernel_launch(void* const* d_in, const int* in_sizes, int n_in,
                              void* d_out, int out_size) {
    const float* x       = (const float*)d_in[0];
    const float* latents = (const float*)d_in[1];
    const float* Wq = (const float*)d_in[2];
    const float* bq = (const float*)d_in[3];
    const float* Wk = (const float*)d_in[4];
    const float* bk = (const float*)d_in[5];
    const float* Wv = (const float*)d_in[6];
    const float* bv = (const float*)d_in[7];
    const float* Wo = (const float*)d_in[8];
    const float* bo = (const float*)d_in[9];
    const float* gamma = (const float*)d_in[10];
    const float* beta  = (const float*)d_in[11];
    const float* rel   = (const float*)d_in[12];
    float* out = (float*)d_out;

    void *pxn, *pQ, *pK, *pV, *pO, *phi, *plo;
    cudaGetSymbolAddress(&pxn, g_xnorm);
    cudaGetSymbolAddress(&pQ, g_Q);
    cudaGetSymbolAddress(&pK, g_K);
    cudaGetSymbolAddress(&pV, g_V);
    cudaGetSymbolAddress(&pO, g_O);
    cudaGetSymbolAddress(&phi, g_Whi);
    cudaGetSymbolAddress(&plo, g_Wlo);
    const __nv_bfloat16* whi = (const __nv_bfloat16*)phi;
    const __nv_bfloat16* wlo = (const __nv_bfloat16*)plo;

    cudaFuncSetAttribute(gemm_kernel, cudaFuncAttributeMaxDynamicSharedMemorySize, GEMM_SMEM);
    cudaFuncSetAttribute(attn_kernel, cudaFuncAttributeMaxDynamicSharedMemorySize, ATTN_SMEM);

    prep_weights<<<4096, 256>>>(Wq, Wk, Wv, Wo);
    ln_kernel<<<MQ / 8, 256>>>(x, gamma, beta, (float*)pxn);

    // Q = LN(x) @ Wq + bq     (grid.x = 4 n-tiles, set2 unused)
    gemm_kernel<<<dim3(4, MQ / 128), 256, GEMM_SMEM>>>(
        (const float*)pxn,
        whi + 0 * DIM * DIM, wlo + 0 * DIM * DIM, bq, (float*)pQ,
        whi + 0 * DIM * DIM, wlo + 0 * DIM * DIM, bq, (float*)pQ,
        nullptr, 4);

    // K|V = latents @ {Wk|Wv} fused: grid.x = 8 (0-3 -> K, 4-7 -> V); A read once (L2)
    gemm_kernel<<<dim3(8, MKV / 128), 256, GEMM_SMEM>>>(
        latents,
        whi + 1 * DIM * DIM, wlo + 1 * DIM * DIM, bk, (float*)pK,
        whi + 2 * DIM * DIM, wlo + 2 * DIM * DIM, bv, (float*)pV,
        nullptr, 4);

    attn_kernel<<<B_SZ * NH, 128, ATTN_SMEM>>>(
        (const float*)pQ, (const float*)pK, (const float*)pV, rel, (float*)pO);

    // out = x + (attn_out @ Wo + bo)
    gemm_kernel<<<dim3(4, MQ / 128), 256, GEMM_SMEM>>>(
        (const float*)pO,
        whi + 3 * DIM * DIM, wlo + 3 * DIM * DIM, bo, out,
        whi + 3 * DIM * DIM, wlo + 3 * DIM * DIM, bo, out,
        x, 4);
}

// round 7
// speedup vs baseline: 1.2453x; 1.2453x over previous
#include <cuda_runtime.h>
#include <cuda_bf16.h>
#include <cstdint>

// ======================= constants =======================
#define B_SZ   1024
#define LQ     16
#define LKV    128
#define DIM    512
#define NH     8
#define DH     64

#define MQ     (B_SZ*LQ)     // 16384
#define MKV    (B_SZ*LKV)    // 131072

// ======================= scratch (device globals; no allocs allowed) =======================
__device__ float g_Q[MQ * DIM];
__device__ float g_K[67108864];   // MKV * DIM fp32
__device__ float g_V[67108864];
__device__ __nv_bfloat16 g_xnhi[MQ * DIM];
__device__ __nv_bfloat16 g_xnlo[MQ * DIM];
__device__ __nv_bfloat16 g_lathi[67108864];
__device__ __nv_bfloat16 g_latlo[67108864];
__device__ __nv_bfloat16 g_Ohi[MQ * DIM];
__device__ __nv_bfloat16 g_Olo[MQ * DIM];
__device__ __nv_bfloat16 g_Whi[4 * DIM * DIM];   // transposed [n][k], hi part
__device__ __nv_bfloat16 g_Wlo[4 * DIM * DIM];   // transposed [n][k], lo part

// ======================= helpers =======================
__device__ __forceinline__ uint32_t smem_u32(const void* p) {
    uint32_t a;
    asm("{ .reg .u64 t; cvta.to.shared.u64 t, %1; cvt.u32.u64 %0, t; }" : "=r"(a) : "l"(p));
    return a;
}

#define CP16(dst, src) \
    asm volatile("cp.async.cg.shared.global [%0], [%1], 16;" :: "r"(dst), "l"(src) : "memory")
#define CP_COMMIT() asm volatile("cp.async.commit_group;" ::: "memory")
#define CP_WAIT1()  asm volatile("cp.async.wait_group 1;" ::: "memory")

__device__ __forceinline__ void ldsm_x4(uint32_t* r, uint32_t addr) {
    asm volatile("ldmatrix.sync.aligned.m8n8.x4.shared.b16 {%0,%1,%2,%3}, [%4];"
                 : "=r"(r[0]), "=r"(r[1]), "=r"(r[2]), "=r"(r[3]) : "r"(addr));
}

__device__ __forceinline__ void mma_bf16(float* d, const uint32_t* a, uint32_t b0, uint32_t b1) {
    asm volatile("mma.sync.aligned.m16n8k16.row.col.f32.bf16.bf16.f32 "
                 "{%0,%1,%2,%3}, {%4,%5,%6,%7}, {%8,%9}, {%0,%1,%2,%3};"
                 : "+f"(d[0]), "+f"(d[1]), "+f"(d[2]), "+f"(d[3])
                 : "r"(a[0]), "r"(a[1]), "r"(a[2]), "r"(a[3]), "r"(b0), "r"(b1));
}

// XOR swizzle: row of 64B = 4 chunks of 16B; chunk ^= (row>>1)&3. Conflict-free for
// ldmatrix 8-row phases and 16B staging (bank enumeration verified).
__device__ __forceinline__ uint32_t swz(int row, int kchunk) {
    return (uint32_t)(row * 64 + ((kchunk ^ ((row >> 1) & 3)) << 4));
}

__device__ __forceinline__ void split8_pack(const float* f, uint4& hv, uint4& lv) {
    unsigned short hs[8], ls[8];
#pragma unroll
    for (int i = 0; i < 8; i++) {
        __nv_bfloat16 h = __float2bfloat16(f[i]);
        __nv_bfloat16 l = __float2bfloat16(f[i] - __bfloat162float(h));
        hs[i] = __bfloat16_as_ushort(h);
        ls[i] = __bfloat16_as_ushort(l);
    }
    hv.x = (uint32_t)hs[0] | ((uint32_t)hs[1] << 16);
    hv.y = (uint32_t)hs[2] | ((uint32_t)hs[3] << 16);
    hv.z = (uint32_t)hs[4] | ((uint32_t)hs[5] << 16);
    hv.w = (uint32_t)hs[6] | ((uint32_t)hs[7] << 16);
    lv.x = (uint32_t)ls[0] | ((uint32_t)ls[1] << 16);
    lv.y = (uint32_t)ls[2] | ((uint32_t)ls[3] << 16);
    lv.z = (uint32_t)ls[4] | ((uint32_t)ls[5] << 16);
    lv.w = (uint32_t)ls[6] | ((uint32_t)ls[7] << 16);
}

// ======================= prep: split W^T into bf16 hi/lo =======================
__global__ void prep_weights(const float* __restrict__ Wq, const float* __restrict__ Wk,
                             const float* __restrict__ Wv, const float* __restrict__ Wo) {
    int idx = blockIdx.x * 256 + threadIdx.x;          // 0 .. 4*512*512-1
    int w = idx >> 18;
    int r = idx & 262143;
    int n = r & 511;
    int k = r >> 9;
    const float* W = (w == 0) ? Wq : (w == 1) ? Wk : (w == 2) ? Wv : Wo;
    float v = W[k * DIM + n];
    __nv_bfloat16 h = __float2bfloat16(v);
    float rem = v - __bfloat162float(h);
    g_Whi[w * DIM * DIM + n * DIM + k] = h;
    g_Wlo[w * DIM * DIM + n * DIM + k] = __float2bfloat16(rem);
}

// ======================= split latents to hi/lo bf16 =======================
__global__ void __launch_bounds__(256) split_latents(const float* __restrict__ src) {
    size_t base = ((size_t)blockIdx.x * 256 + threadIdx.x) * 8;
    float f[8];
    float4 f0 = *(const float4*)(src + base);
    float4 f1 = *(const float4*)(src + base + 4);
    f[0] = f0.x; f[1] = f0.y; f[2] = f0.z; f[3] = f0.w;
    f[4] = f1.x; f[5] = f1.y; f[6] = f1.z; f[7] = f1.w;
    uint4 hv, lv;
    split8_pack(f, hv, lv);
    *(uint4*)(g_lathi + base) = hv;
    *(uint4*)(g_latlo + base) = lv;
}

// ======================= LayerNorm -> hi/lo bf16 =======================
__global__ void ln_kernel(const float* __restrict__ x, const float* __restrict__ gamma,
                          const float* __restrict__ beta) {
    int warp = threadIdx.x >> 5;
    int lane = threadIdx.x & 31;
    size_t row = (size_t)blockIdx.x * 8 + warp;
    const float* xr = x + row * DIM;
    float4 v[4];
    float s = 0.f, ss = 0.f;
#pragma unroll
    for (int j = 0; j < 4; j++) {
        v[j] = *(const float4*)(xr + j * 128 + lane * 4);
        s  += v[j].x + v[j].y + v[j].z + v[j].w;
        ss += v[j].x * v[j].x + v[j].y * v[j].y + v[j].z * v[j].z + v[j].w * v[j].w;
    }
#pragma unroll
    for (int o = 16; o > 0; o >>= 1) {
        s  += __shfl_xor_sync(0xFFFFFFFFu, s, o);
        ss += __shfl_xor_sync(0xFFFFFFFFu, ss, o);
    }
    float mu  = s * (1.0f / DIM);
    float var = ss * (1.0f / DIM) - mu * mu;
    float inv = rsqrtf(var + 1e-5f);
#pragma unroll
    for (int j = 0; j < 4; j++) {
        int c = j * 128 + lane * 4;
        float4 g = *(const float4*)(gamma + c);
        float4 be = *(const float4*)(beta + c);
        float r[4];
        r[0] = (v[j].x - mu) * inv * g.x + be.x;
        r[1] = (v[j].y - mu) * inv * g.y + be.y;
        r[2] = (v[j].z - mu) * inv * g.z + be.z;
        r[3] = (v[j].w - mu) * inv * g.w + be.w;
        uint32_t h2[2], l2[2];
#pragma unroll
        for (int p = 0; p < 2; p++) {
            __nv_bfloat16 h0 = __float2bfloat16(r[p*2]);
            __nv_bfloat16 h1 = __float2bfloat16(r[p*2+1]);
            __nv_bfloat16 l0 = __float2bfloat16(r[p*2]   - __bfloat162float(h0));
            __nv_bfloat16 l1 = __float2bfloat16(r[p*2+1] - __bfloat162float(h1));
            h2[p] = (uint32_t)__bfloat16_as_ushort(h0) | ((uint32_t)__bfloat16_as_ushort(h1) << 16);
            l2[p] = (uint32_t)__bfloat16_as_ushort(l0) | ((uint32_t)__bfloat16_as_ushort(l1) << 16);
        }
        *(uint2*)(g_xnhi + row * DIM + c) = make_uint2(h2[0], h2[1]);
        *(uint2*)(g_xnlo + row * DIM + c) = make_uint2(l2[0], l2[1]);
    }
}

// ======================= GEMM: C[M,512] = (Ahi+Alo)[M,512] @ W + bias (+res) ===========
// pure bf16 cp.async, 3-stage, CTA 128x128, BK=32, 256 thr, 3 MMAs per hi/lo product
#define BM 128
#define BN 128
#define BK 32
#define OFF_AHI 0
#define OFF_ALO 8192
#define OFF_BHI 16384
#define OFF_BLO 24576
#define STAGE_BYTES 32768
#define GEMM_SMEM (3 * STAGE_BYTES)

__global__ void __launch_bounds__(256) gemm_kernel(
    const __nv_bfloat16* __restrict__ Ahi, const __nv_bfloat16* __restrict__ Alo,
    const __nv_bfloat16* __restrict__ Bhi1, const __nv_bfloat16* __restrict__ Blo1,
    const float* __restrict__ bias1, float* __restrict__ C1,
    const __nv_bfloat16* __restrict__ Bhi2, const __nv_bfloat16* __restrict__ Blo2,
    const float* __restrict__ bias2, float* __restrict__ C2,
    const float* __restrict__ residual, int nx1)
{
    extern __shared__ char smc[];
    uint32_t sb = smem_u32(smc);
    const int t = threadIdx.x, lane = t & 31, wid = t >> 5;
    const int wm = wid & 1, wn = wid >> 1;        // warp tile 64(m) x 32(n)
    const int m0 = blockIdx.y * BM;

    const __nv_bfloat16 *Bhi, *Blo; const float* bias; float* C;
    int xt = blockIdx.x;
    if (xt < nx1) { Bhi = Bhi1; Blo = Blo1; bias = bias1; C = C1; }
    else          { Bhi = Bhi2; Blo = Blo2; bias = bias2; C = C2; xt -= nx1; }
    const int n0 = xt * BN;

    const int srow = t >> 2, sc = t & 3;          // staging: thread -> (row, 16B chunk)

    auto stage = [&](int s, int k0) {
        uint32_t sbase = sb + (uint32_t)(s % 3) * STAGE_BYTES;
#pragma unroll
        for (int j = 0; j < 2; j++) {
            int row = srow + j * 64;
            uint32_t off = swz(row, sc);
            const __nv_bfloat16* pa = Ahi + (size_t)(m0 + row) * DIM + k0 + sc * 8;
            const __nv_bfloat16* pb = Alo + (size_t)(m0 + row) * DIM + k0 + sc * 8;
            CP16(sbase + OFF_AHI + off, pa);
            CP16(sbase + OFF_ALO + off, pb);
            const __nv_bfloat16* ph = Bhi + (size_t)(n0 + row) * DIM + k0 + sc * 8;
            const __nv_bfloat16* pl = Blo + (size_t)(n0 + row) * DIM + k0 + sc * 8;
            CP16(sbase + OFF_BHI + off, ph);
            CP16(sbase + OFF_BLO + off, pl);
        }
        CP_COMMIT();
    };

    float acc[4][4][4];
#pragma unroll
    for (int i = 0; i < 4; i++)
#pragma unroll
        for (int j = 0; j < 4; j++)
#pragma unroll
            for (int q = 0; q < 4; q++) acc[i][j][q] = 0.f;

    stage(0, 0);
    stage(1, BK);

    for (int s = 0; s < 16; s++) {
        CP_WAIT1();
        __syncthreads();
        if (s + 2 < 16) stage(s + 2, (s + 2) * BK);
        else CP_COMMIT();                            // keep group count uniform
        uint32_t cbase = sb + (uint32_t)(s % 3) * STAGE_BYTES;
#pragma unroll
        for (int k16 = 0; k16 < 2; k16++) {
            uint32_t Ah[4][4], Al[4][4], Bh[2][4], Bl[2][4];
            int khalf = lane >> 4;
#pragma unroll
            for (int mt = 0; mt < 4; mt++) {
                int row = wm * 64 + mt * 16 + (lane & 15);
                uint32_t off = swz(row, k16 * 2 + khalf);
                ldsm_x4(Ah[mt], cbase + OFF_AHI + off);
                ldsm_x4(Al[mt], cbase + OFF_ALO + off);
            }
#pragma unroll
            for (int np = 0; np < 2; np++) {
                int row = wn * 32 + np * 16 + (lane & 15);
                uint32_t off = swz(row, k16 * 2 + khalf);
                ldsm_x4(Bh[np], cbase + OFF_BHI + off);
                ldsm_x4(Bl[np], cbase + OFF_BLO + off);
            }
#pragma unroll
            for (int mt = 0; mt < 4; mt++) {
#pragma unroll
                for (int nt = 0; nt < 4; nt++) {
                    int np = nt >> 1, i = nt & 1;
                    mma_bf16(acc[mt][nt], Ah[mt], Bh[np][i], Bh[np][i + 2]);
                    mma_bf16(acc[mt][nt], Ah[mt], Bl[np][i], Bl[np][i + 2]);
                    mma_bf16(acc[mt][nt], Al[mt], Bh[np][i], Bh[np][i + 2]);
                }
            }
        }
        __syncthreads();
    }

    // ---- epilogue ----
    const int qr = lane >> 2, qc = lane & 3;
#pragma unroll
    for (int mt = 0; mt < 4; mt++) {
#pragma unroll
        for (int nt = 0; nt < 4; nt++) {
            int r = m0 + wm * 64 + mt * 16 + qr;
            int c = n0 + wn * 32 + nt * 8 + qc * 2;
            float b0 = __ldg(bias + c), b1 = __ldg(bias + c + 1);
            float v0 = acc[mt][nt][0] + b0;
            float v1 = acc[mt][nt][1] + b1;
            float v2 = acc[mt][nt][2] + b0;
            float v3 = acc[mt][nt][3] + b1;
            if (residual) {
                float2 r0 = *(const float2*)(residual + (size_t)r * DIM + c);
                float2 r1 = *(const float2*)(residual + (size_t)(r + 8) * DIM + c);
                v0 += r0.x; v1 += r0.y; v2 += r1.x; v3 += r1.y;
            }
            *(float2*)(C + (size_t)r * DIM + c)       = make_float2(v0, v1);
            *(float2*)(C + (size_t)(r + 8) * DIM + c) = make_float2(v2, v3);
        }
    }
}

// ======================= attention: CTA per (b, h), 128 threads ==================
// Qs[16][64] + Ps[16][128] static smem; K/V streamed via L1; conflict-free layouts.
__global__ void __launch_bounds__(128) attn_kernel(
    const float* __restrict__ Q, const float* __restrict__ K, const float* __restrict__ V,
    const float* __restrict__ rel_bias) {
    __shared__ float Qs[16 * 64];
    __shared__ float Ps[16 * 128];
    int t = threadIdx.x;
    int lane = t & 31;
    int bh = blockIdx.x;
    int b = bh >> 3, h = bh & 7;

    {   // load Q tile 16x64
        int q = t >> 3, c = (t & 7) * 8;
        const float* Qg = Q + ((size_t)(b * LQ + q)) * DIM + h * DH + c;
        float4 v0 = *(const float4*)Qg;
        float4 v1 = *(const float4*)(Qg + 4);
        *(float4*)(Qs + q * 64 + c)     = v0;
        *(float4*)(Qs + q * 64 + c + 4) = v1;
    }
    __syncthreads();

    // ---- scores: thread owns kv = t ----
    {
        const float4* Kr = (const float4*)(K + ((size_t)(b * LKV + t)) * DIM + h * DH);
        float acc[16];
#pragma unroll
        for (int q = 0; q < 16; q++) acc[q] = 0.f;
#pragma unroll
        for (int dc = 0; dc < 4; dc++) {
            float4 kk[4];
#pragma unroll
            for (int i = 0; i < 4; i++) kk[i] = Kr[dc * 4 + i];
#pragma unroll
            for (int q = 0; q < 16; q++) {
                const float4* qp = (const float4*)(Qs + q * 64 + dc * 16);
#pragma unroll
                for (int i = 0; i < 4; i++) {
                    float4 qv = qp[i];
                    acc[q] += kk[i].x * qv.x + kk[i].y * qv.y + kk[i].z * qv.z + kk[i].w * qv.w;
                }
            }
        }
        const float* bsrc = rel_bias + ((size_t)h * LQ) * LKV + t;
#pragma unroll
        for (int q = 0; q < 16; q++)
            Ps[q * 128 + t] = acc[q] * 0.125f + bsrc[q * LKV];
    }
    __syncthreads();

    // ---- softmax: warp w handles rows 4w..4w+3; lane covers kv = lane*4.. ----
    {
        int w = t >> 5;
#pragma unroll
        for (int qq = 0; qq < 4; qq++) {
            int q = w * 4 + qq;
            float4 pv = *(float4*)(Ps + q * 128 + lane * 4);
            float m = fmaxf(fmaxf(pv.x, pv.y), fmaxf(pv.z, pv.w));
#pragma unroll
            for (int o = 16; o > 0; o >>= 1) m = fmaxf(m, __shfl_xor_sync(0xFFFFFFFFu, m, o));
            pv.x = __expf(pv.x - m); pv.y = __expf(pv.y - m);
            pv.z = __expf(pv.z - m); pv.w = __expf(pv.w - m);
            float s = pv.x + pv.y + pv.z + pv.w;
#pragma unroll
            for (int o = 16; o > 0; o >>= 1) s += __shfl_xor_sync(0xFFFFFFFFu, s, o);
            float inv = 1.0f / s;
            pv.x *= inv; pv.y *= inv; pv.z *= inv; pv.w *= inv;
            *(float4*)(Ps + q * 128 + lane * 4) = pv;
        }
    }
    __syncthreads();

    // ---- PV: thread owns (qhalf = t>>6, d = t&63) ----
    {
        int d = t & 63, qh = t >> 6;
        const float* Vb = V + ((size_t)(b * LKV)) * DIM + h * DH + d;
        float o[8];
#pragma unroll
        for (int j = 0; j < 8; j++) o[j] = 0.f;
        for (int kv4 = 0; kv4 < 32; kv4++) {
            float vv0 = Vb[(size_t)(kv4 * 4 + 0) * DIM];
            float vv1 = Vb[(size_t)(kv4 * 4 + 1) * DIM];
            float vv2 = Vb[(size_t)(kv4 * 4 + 2) * DIM];
            float vv3 = Vb[(size_t)(kv4 * 4 + 3) * DIM];
#pragma unroll
            for (int j = 0; j < 8; j++) {
                float4 p = *(float4*)(Ps + (qh * 8 + j) * 128 + kv4 * 4);
                o[j] += p.x * vv0 + p.y * vv1 + p.z * vv2 + p.w * vv3;
            }
        }
#pragma unroll
        for (int j = 0; j < 8; j++) {
            size_t row = (size_t)(b * LQ + qh * 8 + j);
            __nv_bfloat16 hi = __float2bfloat16(o[j]);
            __nv_bfloat16 lo = __float2bfloat16(o[j] - __bfloat162float(hi));
            g_Ohi[row * DIM + h * DH + d] = hi;
            g_Olo[row * DIM + h * DH + d] = lo;
        }
    }
}

// ======================= launch =======================
extern "C" void kernel_launch(void* const* d_in, const int* in_sizes, int n_in,
                              void* d_out, int out_size) {
    const float* x       = (const float*)d_in[0];
    const float* latents = (const float*)d_in[1];
    const float* Wq = (const float*)d_in[2];
    const float* bq = (const float*)d_in[3];
    const float* Wk = (const float*)d_in[4];
    const float* bk = (const float*)d_in[5];
    const float* Wv = (const float*)d_in[6];
    const float* bv = (const float*)d_in[7];
    const float* Wo = (const float*)d_in[8];
    const float* bo = (const float*)d_in[9];
    const float* gamma = (const float*)d_in[10];
    const float* beta  = (const float*)d_in[11];
    const float* rel   = (const float*)d_in[12];
    float* out = (float*)d_out;

    void *pQ, *pK, *pV, *phi, *plo, *pxh, *pxl, *plh, *pll, *poh, *pol;
    cudaGetSymbolAddress(&pQ, g_Q);
    cudaGetSymbolAddress(&pK, g_K);
    cudaGetSymbolAddress(&pV, g_V);
    cudaGetSymbolAddress(&phi, g_Whi);
    cudaGetSymbolAddress(&plo, g_Wlo);
    cudaGetSymbolAddress(&pxh, g_xnhi);
    cudaGetSymbolAddress(&pxl, g_xnlo);
    cudaGetSymbolAddress(&plh, g_lathi);
    cudaGetSymbolAddress(&pll, g_latlo);
    cudaGetSymbolAddress(&poh, g_Ohi);
    cudaGetSymbolAddress(&pol, g_Olo);
    const __nv_bfloat16* whi = (const __nv_bfloat16*)phi;
    const __nv_bfloat16* wlo = (const __nv_bfloat16*)plo;

    cudaFuncSetAttribute(gemm_kernel, cudaFuncAttributeMaxDynamicSharedMemorySize, GEMM_SMEM);

    prep_weights<<<4096, 256>>>(Wq, Wk, Wv, Wo);
    ln_kernel<<<MQ / 8, 256>>>(x, gamma, beta);
    split_latents<<<(MKV * DIM) / (256 * 8), 256>>>(latents);

    // Q = LN(x) @ Wq + bq
    gemm_kernel<<<dim3(4, MQ / 128), 256, GEMM_SMEM>>>(
        (const __nv_bfloat16*)pxh, (const __nv_bfloat16*)pxl,
        whi + 0 * DIM * DIM, wlo + 0 * DIM * DIM, bq, (float*)pQ,
        whi + 0 * DIM * DIM, wlo + 0 * DIM * DIM, bq, (float*)pQ,
        nullptr, 4);

    // K|V = latents @ {Wk|Wv}: grid.x = 8 (0-3 -> K, 4-7 -> V); A re-read via L2
    gemm_kernel<<<dim3(8, MKV / 128), 256, GEMM_SMEM>>>(
        (const __nv_bfloat16*)plh, (const __nv_bfloat16*)pll,
        whi + 1 * DIM * DIM, wlo + 1 * DIM * DIM, bk, (float*)pK,
        whi + 2 * DIM * DIM, wlo + 2 * DIM * DIM, bv, (float*)pV,
        nullptr, 4);

    attn_kernel<<<B_SZ * NH, 128>>>(
        (const float*)pQ, (const float*)pK, (const float*)pV, rel);

    // out = x + (attn_out @ Wo + bo)
    gemm_kernel<<<dim3(4, MQ / 128), 256, GEMM_SMEM>>>(
        (const __nv_bfloat16*)poh, (const __nv_bfloat16*)pol,
        whi + 3 * DIM * DIM, wlo + 3 * DIM * DIM, bo, out,
        whi + 3 * DIM * DIM, wlo + 3 * DIM * DIM, bo, out,
        x, 4);
}

// round 10
// speedup vs baseline: 2.3787x; 1.9101x over previous
#include <cuda_runtime.h>
#include <cuda_fp16.h>
#include <cstdint>

// ======================= constants =======================
#define B_SZ   1024
#define LQ     16
#define LKV    128
#define DIM    512
#define NH     8
#define DH     64

#define MQ     (B_SZ*LQ)     // 16384
#define MKV    (B_SZ*LKV)    // 131072

// ======================= scratch (device globals; no allocs allowed) =======================
__device__ float g_Q[MQ * DIM];
__device__ float g_K[67108864];   // MKV * DIM fp32
__device__ float g_V[67108864];
__device__ __half g_xn16[MQ * DIM];
__device__ __half g_lat16[67108864];
__device__ __half g_O16[MQ * DIM];
__device__ __half g_W16[4 * DIM * DIM];   // transposed [n][k]

// ======================= helpers =======================
__device__ __forceinline__ uint32_t smem_u32(const void* p) {
    uint32_t a;
    asm("{ .reg .u64 t; cvta.to.shared.u64 t, %1; cvt.u32.u64 %0, t; }" : "=r"(a) : "l"(p));
    return a;
}

#define CP16(dst, src) \
    asm volatile("cp.async.cg.shared.global [%0], [%1], 16;" :: "r"(dst), "l"(src) : "memory")
#define CP_COMMIT() asm volatile("cp.async.commit_group;" ::: "memory")
#define CP_WAIT2()  asm volatile("cp.async.wait_group 2;" ::: "memory")

__device__ __forceinline__ void ldsm_x4(uint32_t* r, uint32_t addr) {
    asm volatile("ldmatrix.sync.aligned.m8n8.x4.shared.b16 {%0,%1,%2,%3}, [%4];"
                 : "=r"(r[0]), "=r"(r[1]), "=r"(r[2]), "=r"(r[3]) : "r"(addr));
}

__device__ __forceinline__ void mma_f16(float* d, const uint32_t* a, uint32_t b0, uint32_t b1) {
    asm volatile("mma.sync.aligned.m16n8k16.row.col.f32.f16.f16.f32 "
                 "{%0,%1,%2,%3}, {%4,%5,%6,%7}, {%8,%9}, {%0,%1,%2,%3};"
                 : "+f"(d[0]), "+f"(d[1]), "+f"(d[2]), "+f"(d[3])
                 : "r"(a[0]), "r"(a[1]), "r"(a[2]), "r"(a[3]), "r"(b0), "r"(b1));
}

// XOR swizzle: row of 64B = 4 chunks of 16B; chunk ^= (row>>1)&3. Conflict-free for
// ldmatrix 8-row phases and 16B staging (bank enumeration verified).
__device__ __forceinline__ uint32_t swz(int row, int kchunk) {
    return (uint32_t)(row * 64 + ((kchunk ^ ((row >> 1) & 3)) << 4));
}

// ======================= prep: W^T -> fp16 =======================
__global__ void prep_weights(const float* __restrict__ Wq, const float* __restrict__ Wk,
                             const float* __restrict__ Wv, const float* __restrict__ Wo) {
    int idx = blockIdx.x * 256 + threadIdx.x;          // 0 .. 4*512*512-1
    int w = idx >> 18;
    int r = idx & 262143;
    int n = r & 511;
    int k = r >> 9;
    const float* W = (w == 0) ? Wq : (w == 1) ? Wk : (w == 2) ? Wv : Wo;
    g_W16[w * DIM * DIM + n * DIM + k] = __float2half_rn(W[k * DIM + n]);
}

// ======================= latents -> fp16 =======================
__global__ void __launch_bounds__(256) conv_latents(const float* __restrict__ src) {
    size_t base = ((size_t)blockIdx.x * 256 + threadIdx.x) * 8;
    float4 f0 = *(const float4*)(src + base);
    float4 f1 = *(const float4*)(src + base + 4);
    __half2 h[4];
    h[0] = __floats2half2_rn(f0.x, f0.y);
    h[1] = __floats2half2_rn(f0.z, f0.w);
    h[2] = __floats2half2_rn(f1.x, f1.y);
    h[3] = __floats2half2_rn(f1.z, f1.w);
    *(uint4*)(g_lat16 + base) = *(uint4*)h;
}

// ======================= LayerNorm -> fp16 =======================
__global__ void ln_kernel(const float* __restrict__ x, const float* __restrict__ gamma,
                          const float* __restrict__ beta) {
    int warp = threadIdx.x >> 5;
    int lane = threadIdx.x & 31;
    size_t row = (size_t)blockIdx.x * 8 + warp;
    const float* xr = x + row * DIM;
    float4 v[4];
    float s = 0.f, ss = 0.f;
#pragma unroll
    for (int j = 0; j < 4; j++) {
        v[j] = *(const float4*)(xr + j * 128 + lane * 4);
        s  += v[j].x + v[j].y + v[j].z + v[j].w;
        ss += v[j].x * v[j].x + v[j].y * v[j].y + v[j].z * v[j].z + v[j].w * v[j].w;
    }
#pragma unroll
    for (int o = 16; o > 0; o >>= 1) {
        s  += __shfl_xor_sync(0xFFFFFFFFu, s, o);
        ss += __shfl_xor_sync(0xFFFFFFFFu, ss, o);
    }
    float mu  = s * (1.0f / DIM);
    float var = ss * (1.0f / DIM) - mu * mu;
    float inv = rsqrtf(var + 1e-5f);
#pragma unroll
    for (int j = 0; j < 4; j++) {
        int c = j * 128 + lane * 4;
        float4 g = *(const float4*)(gamma + c);
        float4 be = *(const float4*)(beta + c);
        __half2 h[2];
        h[0] = __floats2half2_rn((v[j].x - mu) * inv * g.x + be.x,
                                 (v[j].y - mu) * inv * g.y + be.y);
        h[1] = __floats2half2_rn((v[j].z - mu) * inv * g.z + be.z,
                                 (v[j].w - mu) * inv * g.w + be.w);
        *(uint2*)(g_xn16 + row * DIM + c) = *(uint2*)h;
    }
}

// ======================= GEMM: C[M,512] = A16[M,512] @ W16 + bias (+res) ===========
// single fp16 MMA, cp.async 4-stage, CTA 128x128, BK=32, 256 thr
#define BM 128
#define BN 128
#define BK 32
#define OFF_A 0
#define OFF_B 8192
#define STAGE_BYTES 16384
#define NSTAGE 4
#define GEMM_SMEM (NSTAGE * STAGE_BYTES)

__global__ void __launch_bounds__(256) gemm_kernel(
    const __half* __restrict__ A,
    const __half* __restrict__ B1, const float* __restrict__ bias1, float* __restrict__ C1,
    const __half* __restrict__ B2, const float* __restrict__ bias2, float* __restrict__ C2,
    const float* __restrict__ residual, int nx1)
{
    extern __shared__ char smc[];
    uint32_t sb = smem_u32(smc);
    const int t = threadIdx.x, lane = t & 31, wid = t >> 5;
    const int wm = wid & 1, wn = wid >> 1;        // warp tile 64(m) x 32(n)
    const int m0 = blockIdx.y * BM;

    const __half* B; const float* bias; float* C;
    int xt = blockIdx.x;
    if (xt < nx1) { B = B1; bias = bias1; C = C1; }
    else          { B = B2; bias = bias2; C = C2; xt -= nx1; }
    const int n0 = xt * BN;

    const int srow = t >> 2, sc = t & 3;          // staging: thread -> (row, 16B chunk)

    auto stage = [&](int s, int k0) {
        uint32_t sbase = sb + (uint32_t)(s & (NSTAGE - 1)) * STAGE_BYTES;
#pragma unroll
        for (int j = 0; j < 2; j++) {
            int row = srow + j * 64;
            uint32_t off = swz(row, sc);
            CP16(sbase + OFF_A + off, A + (size_t)(m0 + row) * DIM + k0 + sc * 8);
            CP16(sbase + OFF_B + off, B + (size_t)(n0 + row) * DIM + k0 + sc * 8);
        }
        CP_COMMIT();
    };

    float acc[4][4][4];
#pragma unroll
    for (int i = 0; i < 4; i++)
#pragma unroll
        for (int j = 0; j < 4; j++)
#pragma unroll
            for (int q = 0; q < 4; q++) acc[i][j][q] = 0.f;

    stage(0, 0);
    stage(1, BK);
    stage(2, 2 * BK);

    for (int s = 0; s < 16; s++) {
        CP_WAIT2();
        __syncthreads();
        if (s + 3 < 16) stage(s + 3, (s + 3) * BK);
        else CP_COMMIT();                          // uniform group accounting
        uint32_t cbase = sb + (uint32_t)(s & (NSTAGE - 1)) * STAGE_BYTES;
#pragma unroll
        for (int k16 = 0; k16 < 2; k16++) {
            uint32_t Af[4][4], Bf[2][4];
            int khalf = lane >> 4;
#pragma unroll
            for (int mt = 0; mt < 4; mt++) {
                int row = wm * 64 + mt * 16 + (lane & 15);
                ldsm_x4(Af[mt], cbase + OFF_A + swz(row, k16 * 2 + khalf));
            }
#pragma unroll
            for (int np = 0; np < 2; np++) {
                int row = wn * 32 + np * 16 + (lane & 15);
                ldsm_x4(Bf[np], cbase + OFF_B + swz(row, k16 * 2 + khalf));
            }
#pragma unroll
            for (int mt = 0; mt < 4; mt++) {
#pragma unroll
                for (int nt = 0; nt < 4; nt++) {
                    int np = nt >> 1, i = nt & 1;
                    mma_f16(acc[mt][nt], Af[mt], Bf[np][i], Bf[np][i + 2]);
                }
            }
        }
    }

    // ---- epilogue ----
    __syncthreads();
    const int qr = lane >> 2, qc = lane & 3;
#pragma unroll
    for (int mt = 0; mt < 4; mt++) {
#pragma unroll
        for (int nt = 0; nt < 4; nt++) {
            int r = m0 + wm * 64 + mt * 16 + qr;
            int c = n0 + wn * 32 + nt * 8 + qc * 2;
            float b0 = __ldg(bias + c), b1 = __ldg(bias + c + 1);
            float v0 = acc[mt][nt][0] + b0;
            float v1 = acc[mt][nt][1] + b1;
            float v2 = acc[mt][nt][2] + b0;
            float v3 = acc[mt][nt][3] + b1;
            if (residual) {
                float2 r0 = *(const float2*)(residual + (size_t)r * DIM + c);
                float2 r1 = *(const float2*)(residual + (size_t)(r + 8) * DIM + c);
                v0 += r0.x; v1 += r0.y; v2 += r1.x; v3 += r1.y;
            }
            *(float2*)(C + (size_t)r * DIM + c)       = make_float2(v0, v1);
            *(float2*)(C + (size_t)(r + 8) * DIM + c) = make_float2(v2, v3);
        }
    }
}

// ======================= attention: CTA per (b, h), 128 threads ==================
// Qs[16][64] + Ps[16][128] static smem; K/V streamed via L1; conflict-free layouts.
__global__ void __launch_bounds__(128) attn_kernel(
    const float* __restrict__ Q, const float* __restrict__ K, const float* __restrict__ V,
    const float* __restrict__ rel_bias) {
    __shared__ float Qs[16 * 64];
    __shared__ float Ps[16 * 128];
    int t = threadIdx.x;
    int lane = t & 31;
    int bh = blockIdx.x;
    int b = bh >> 3, h = bh & 7;

    {   // load Q tile 16x64
        int q = t >> 3, c = (t & 7) * 8;
        const float* Qg = Q + ((size_t)(b * LQ + q)) * DIM + h * DH + c;
        float4 v0 = *(const float4*)Qg;
        float4 v1 = *(const float4*)(Qg + 4);
        *(float4*)(Qs + q * 64 + c)     = v0;
        *(float4*)(Qs + q * 64 + c + 4) = v1;
    }
    __syncthreads();

    // ---- scores: thread owns kv = t ----
    {
        const float4* Kr = (const float4*)(K + ((size_t)(b * LKV + t)) * DIM + h * DH);
        float acc[16];
#pragma unroll
        for (int q = 0; q < 16; q++) acc[q] = 0.f;
#pragma unroll
        for (int dc = 0; dc < 4; dc++) {
            float4 kk[4];
#pragma unroll
            for (int i = 0; i < 4; i++) kk[i] = Kr[dc * 4 + i];
#pragma unroll
            for (int q = 0; q < 16; q++) {
                const float4* qp = (const float4*)(Qs + q * 64 + dc * 16);
#pragma unroll
                for (int i = 0; i < 4; i++) {
                    float4 qv = qp[i];
                    acc[q] += kk[i].x * qv.x + kk[i].y * qv.y + kk[i].z * qv.z + kk[i].w * qv.w;
                }
            }
        }
        const float* bsrc = rel_bias + ((size_t)h * LQ) * LKV + t;
#pragma unroll
        for (int q = 0; q < 16; q++)
            Ps[q * 128 + t] = acc[q] * 0.125f + bsrc[q * LKV];
    }
    __syncthreads();

    // ---- softmax: warp w handles rows 4w..4w+3 ----
    {
        int w = t >> 5;
#pragma unroll
        for (int qq = 0; qq < 4; qq++) {
            int q = w * 4 + qq;
            float4 pv = *(float4*)(Ps + q * 128 + lane * 4);
            float m = fmaxf(fmaxf(pv.x, pv.y), fmaxf(pv.z, pv.w));
#pragma unroll
            for (int o = 16; o > 0; o >>= 1) m = fmaxf(m, __shfl_xor_sync(0xFFFFFFFFu, m, o));
            pv.x = __expf(pv.x - m); pv.y = __expf(pv.y - m);
            pv.z = __expf(pv.z - m); pv.w = __expf(pv.w - m);
            float s = pv.x + pv.y + pv.z + pv.w;
#pragma unroll
            for (int o = 16; o > 0; o >>= 1) s += __shfl_xor_sync(0xFFFFFFFFu, s, o);
            float inv = 1.0f / s;
            pv.x *= inv; pv.y *= inv; pv.z *= inv; pv.w *= inv;
            *(float4*)(Ps + q * 128 + lane * 4) = pv;
        }
    }
    __syncthreads();

    // ---- PV: thread owns (qhalf = t>>6, d = t&63); out -> fp16 ----
    {
        int d = t & 63, qh = t >> 6;
        const float* Vb = V + ((size_t)(b * LKV)) * DIM + h * DH + d;
        float o[8];
#pragma unroll
        for (int j = 0; j < 8; j++) o[j] = 0.f;
        for (int kv4 = 0; kv4 < 32; kv4++) {
            float vv0 = Vb[(size_t)(kv4 * 4 + 0) * DIM];
            float vv1 = Vb[(size_t)(kv4 * 4 + 1) * DIM];
            float vv2 = Vb[(size_t)(kv4 * 4 + 2) * DIM];
            float vv3 = Vb[(size_t)(kv4 * 4 + 3) * DIM];
#pragma unroll
            for (int j = 0; j < 8; j++) {
                float4 p = *(float4*)(Ps + (qh * 8 + j) * 128 + kv4 * 4);
                o[j] += p.x * vv0 + p.y * vv1 + p.z * vv2 + p.w * vv3;
            }
        }
#pragma unroll
        for (int j = 0; j < 8; j++) {
            size_t row = (size_t)(b * LQ + qh * 8 + j);
            g_O16[row * DIM + h * DH + d] = __float2half_rn(o[j]);
        }
    }
}

// ======================= launch =======================
extern "C" void kernel_launch(void* const* d_in, const int* in_sizes, int n_in,
                              void* d_out, int out_size) {
    const float* x       = (const float*)d_in[0];
    const float* latents = (const float*)d_in[1];
    const float* Wq = (const float*)d_in[2];
    const float* bq = (const float*)d_in[3];
    const float* Wk = (const float*)d_in[4];
    const float* bk = (const float*)d_in[5];
    const float* Wv = (const float*)d_in[6];
    const float* bv = (const float*)d_in[7];
    const float* Wo = (const float*)d_in[8];
    const float* bo = (const float*)d_in[9];
    const float* gamma = (const float*)d_in[10];
    const float* beta  = (const float*)d_in[11];
    const float* rel   = (const float*)d_in[12];
    float* out = (float*)d_out;

    void *pQ, *pK, *pV, *pw, *pxn, *plat, *po16;
    cudaGetSymbolAddress(&pQ, g_Q);
    cudaGetSymbolAddress(&pK, g_K);
    cudaGetSymbolAddress(&pV, g_V);
    cudaGetSymbolAddress(&pw, g_W16);
    cudaGetSymbolAddress(&pxn, g_xn16);
    cudaGetSymbolAddress(&plat, g_lat16);
    cudaGetSymbolAddress(&po16, g_O16);
    const __half* w16 = (const __half*)pw;

    cudaFuncSetAttribute(gemm_kernel, cudaFuncAttributeMaxDynamicSharedMemorySize, GEMM_SMEM);

    prep_weights<<<4096, 256>>>(Wq, Wk, Wv, Wo);
    ln_kernel<<<MQ / 8, 256>>>(x, gamma, beta);
    conv_latents<<<(MKV * DIM) / (256 * 8), 256>>>(latents);

    // Q = LN(x) @ Wq + bq
    gemm_kernel<<<dim3(4, MQ / 128), 256, GEMM_SMEM>>>(
        (const __half*)pxn,
        w16 + 0 * DIM * DIM, bq, (float*)pQ,
        w16 + 0 * DIM * DIM, bq, (float*)pQ,
        nullptr, 4);

    // K|V = latents @ {Wk|Wv}: grid.x = 8 (0-3 -> K, 4-7 -> V)
    gemm_kernel<<<dim3(8, MKV / 128), 256, GEMM_SMEM>>>(
        (const __half*)plat,
        w16 + 1 * DIM * DIM, bk, (float*)pK,
        w16 + 2 * DIM * DIM, bv, (float*)pV,
        nullptr, 4);

    attn_kernel<<<B_SZ * NH, 128>>>(
        (const float*)pQ, (const float*)pK, (const float*)pV, rel);

    // out = x + (attn_out @ Wo + bo)
    gemm_kernel<<<dim3(4, MQ / 128), 256, GEMM_SMEM>>>(
        (const __half*)po16,
        w16 + 3 * DIM * DIM, bo, out,
        w16 + 3 * DIM * DIM, bo, out,
        x, 4);
}